// round 10
// baseline (speedup 1.0000x reference)
#include <cuda_runtime.h>
#include <cuda_fp16.h>

#define NN   50000
#define EE   800000
#define IN_F 128
#define OUT_F 64
#define MAPF 64
#define NH   4
#define SCAN_BS 512
#define NB ((NN + SCAN_BS - 1) / SCAN_BS)   // 98

// ---------------- scratch (static device globals; no allocation) ----------------
__device__ int   g_count[NN];
__device__ int   g_off[NN + 1];
__device__ int   g_cursor[NN];
__device__ int   g_bsum[NB];
__device__ int   g_bbase[NB];
__device__ int   g_srcs[EE];
__device__ unsigned g_zh[NN * 32];   // z as fp16: 64 halfs/row
__device__ uint2    g_fh[NN * 64];   // feat as fp16: 256 halfs/row ([h][64])
__device__ float4 g_eg[NN * 2];      // [2n] = el(4 heads), [2n+1] = gx3 = x@W_gate[192:320]
__device__ float4 g_er4[NN];         // er (4 heads)
__device__ float4 g_gx1[NN];         // x@W_gate[0:128]
__device__ float g_gated[NN * OUT_F];

// ---------------- helpers ----------------
__device__ __forceinline__ void hmma16(float* c, unsigned a0, unsigned a1, unsigned a2,
                                       unsigned a3, unsigned b0, unsigned b1) {
    asm volatile(
        "mma.sync.aligned.m16n8k16.row.col.f32.f16.f16.f32 "
        "{%0,%1,%2,%3},{%4,%5,%6,%7},{%8,%9},{%0,%1,%2,%3};"
        : "+f"(c[0]), "+f"(c[1]), "+f"(c[2]), "+f"(c[3])
        : "r"(a0), "r"(a1), "r"(a2), "r"(a3), "r"(b0), "r"(b1));
}
__device__ __forceinline__ unsigned packh2(float a, float b) {
    __half2 h = __floats2half2_rn(a, b);
    return *(unsigned*)&h;
}
__device__ __forceinline__ float2 unpackh2(unsigned u) {
    return __half22float2(*(__half2*)&u);
}

// ---------------- CSR build ----------------
__global__ void k_zero() {
    int i = blockIdx.x * blockDim.x + threadIdx.x;
    if (i < NN) g_count[i] = 0;
}

__global__ void k_hist(const int* __restrict__ dst) {
    int e4 = blockIdx.x * blockDim.x + threadIdx.x;
    if (e4 < EE / 4) {
        int4 d = ((const int4*)dst)[e4];
        atomicAdd(&g_count[d.x], 1);
        atomicAdd(&g_count[d.y], 1);
        atomicAdd(&g_count[d.z], 1);
        atomicAdd(&g_count[d.w], 1);
    }
}

__global__ void k_scan1() {
    __shared__ int wsum[16];
    int b = blockIdx.x, t = threadIdx.x, lane = t & 31, w = t >> 5;
    int i = b * SCAN_BS + t;
    int v = (i < NN) ? g_count[i] : 0;
    int xs = v;
    #pragma unroll
    for (int d = 1; d < 32; d <<= 1) {
        int y = __shfl_up_sync(0xffffffffu, xs, d);
        if (lane >= d) xs += y;
    }
    if (lane == 31) wsum[w] = xs;
    __syncthreads();
    if (w == 0) {
        int s = (lane < 16) ? wsum[lane] : 0;
        #pragma unroll
        for (int d = 1; d < 16; d <<= 1) {
            int y = __shfl_up_sync(0xffffffffu, s, d);
            if (lane >= d) s += y;
        }
        if (lane < 16) wsum[lane] = s;
    }
    __syncthreads();
    int base = (w > 0) ? wsum[w - 1] : 0;
    if (i < NN) g_off[i] = base + xs - v;
    if (t == SCAN_BS - 1) g_bsum[b] = wsum[15];
}

__global__ void k_scan2() {
    __shared__ int ws[4];
    int t = threadIdx.x, lane = t & 31, w = t >> 5;
    int v = (t < NB) ? g_bsum[t] : 0;
    int xs = v;
    #pragma unroll
    for (int d = 1; d < 32; d <<= 1) {
        int y = __shfl_up_sync(0xffffffffu, xs, d);
        if (lane >= d) xs += y;
    }
    if (lane == 31) ws[w] = xs;
    __syncthreads();
    if (t == 0) {
        int a = 0;
        #pragma unroll
        for (int k = 0; k < 4; k++) { int tmp = ws[k]; ws[k] = a; a += tmp; }
    }
    __syncthreads();
    if (t < NB) g_bbase[t] = ws[w] + xs - v;
}

__global__ void k_scan3() {
    int b = blockIdx.x, t = threadIdx.x;
    int i = b * SCAN_BS + t;
    if (i < NN) {
        int o = g_off[i] + g_bbase[b];
        g_off[i] = o;
        g_cursor[i] = o;
    }
    if (i == 0) g_off[NN] = EE;
}

__global__ void k_scatter(const int* __restrict__ src, const int* __restrict__ dst) {
    int e4 = blockIdx.x * blockDim.x + threadIdx.x;
    if (e4 < EE / 4) {
        int4 d = ((const int4*)dst)[e4];
        int4 s = ((const int4*)src)[e4];
        g_srcs[atomicAdd(&g_cursor[d.x], 1)] = s.x;
        g_srcs[atomicAdd(&g_cursor[d.y], 1)] = s.y;
        g_srcs[atomicAdd(&g_cursor[d.z], 1)] = s.z;
        g_srcs[atomicAdd(&g_cursor[d.w], 1)] = s.w;
    }
}

// ---------------- GEMM1 (fp16 HMMA m16n8k16): z_h (nt=0), feat_h (nt=1..4) -----------
__global__ void k_gemm1(const float* __restrict__ x,
                        const float* __restrict__ Wgm, const float* __restrict__ bgm,
                        const float* __restrict__ Wfc) {
    __shared__ unsigned Ah[128][12];
    __shared__ unsigned Bs[8][72];
    int t = threadIdx.x;
    int nt = blockIdx.y;
    int rowBase = blockIdx.x * 128;
    const float* W; int ldw, colBase;
    if (nt == 0) { W = Wgm; ldw = 64;  colBase = 0; }
    else         { W = Wfc; ldw = 256; colBase = (nt - 1) * 64; }

    int lane = t & 31, wrp = t >> 5;
    int wm = wrp & 3, wn = wrp >> 2;
    int g = lane >> 2, tig = lane & 3;

    float acc[2][4][4];
    #pragma unroll
    for (int mi = 0; mi < 2; mi++)
        #pragma unroll
        for (int ni = 0; ni < 4; ni++)
            #pragma unroll
            for (int q = 0; q < 4; q++) acc[mi][ni][q] = 0.f;

    int ar0 = t >> 2, akq = t & 3;
    int ar1 = ar0 + 64;
    int gr0 = rowBase + ar0; if (gr0 >= NN) gr0 = NN - 1;
    int gr1 = rowBase + ar1; if (gr1 >= NN) gr1 = NN - 1;
    int bkk = t >> 5, bl = t & 31;
    int n2 = bl * 2;

    for (int kt = 0; kt < 8; kt++) {
        float4 a0v = *(const float4*)&x[gr0 * IN_F + kt * 16 + akq * 4];
        float4 a1v = *(const float4*)&x[gr1 * IN_F + kt * 16 + akq * 4];
        float2 bv0 = *(const float2*)&W[(kt * 16 + 2 * bkk) * ldw + colBase + n2];
        float2 bv1 = *(const float2*)&W[(kt * 16 + 2 * bkk + 1) * ldw + colBase + n2];
        uint2 ua0 = {packh2(a0v.x, a0v.y), packh2(a0v.z, a0v.w)};
        uint2 ua1 = {packh2(a1v.x, a1v.y), packh2(a1v.z, a1v.w)};
        uint2 ubv = {packh2(bv0.x, bv1.x), packh2(bv0.y, bv1.y)};
        *(uint2*)&Ah[ar0][akq * 2] = ua0;
        *(uint2*)&Ah[ar1][akq * 2] = ua1;
        *(uint2*)&Bs[bkk][n2]      = ubv;
        __syncthreads();
        unsigned a[2][4];
        #pragma unroll
        for (int mi = 0; mi < 2; mi++) {
            int rm = wm * 32 + mi * 16;
            a[mi][0] = Ah[rm + g][tig];
            a[mi][1] = Ah[rm + g + 8][tig];
            a[mi][2] = Ah[rm + g][tig + 4];
            a[mi][3] = Ah[rm + g + 8][tig + 4];
        }
        #pragma unroll
        for (int ni = 0; ni < 4; ni++) {
            int cn = wn * 32 + ni * 8;
            unsigned b0 = Bs[tig][cn + g];
            unsigned b1 = Bs[tig + 4][cn + g];
            hmma16(acc[0][ni], a[0][0], a[0][1], a[0][2], a[0][3], b0, b1);
            hmma16(acc[1][ni], a[1][0], a[1][1], a[1][2], a[1][3], b0, b1);
        }
        __syncthreads();
    }

    #pragma unroll
    for (int mi = 0; mi < 2; mi++) {
        #pragma unroll
        for (int ni = 0; ni < 4; ni++) {
            int lc = wn * 32 + ni * 8 + tig * 2;
            #pragma unroll
            for (int half = 0; half < 2; half++) {
                int r = rowBase + wm * 32 + mi * 16 + g + half * 8;
                if (r < NN) {
                    float v0 = acc[mi][ni][half * 2 + 0];
                    float v1 = acc[mi][ni][half * 2 + 1];
                    if (nt == 0) {
                        g_zh[r * 32 + (lc >> 1)] = packh2(v0 + bgm[lc], v1 + bgm[lc + 1]);
                    } else {
                        ((unsigned*)g_fh)[r * 128 + ((colBase + lc) >> 1)] = packh2(v0, v1);
                    }
                }
            }
        }
    }
}

// ---------------- k_pre: el/er + gx1/gx3 per node (warp per node) ----------------
__global__ void k_pre(const float* __restrict__ x,
                      const float* __restrict__ al, const float* __restrict__ ar,
                      const float* __restrict__ Wg) {
    __shared__ float sW1[IN_F * NH];   // W_gate rows 0..127
    __shared__ float sW3[IN_F * NH];   // W_gate rows 192..319
    for (int i = threadIdx.x; i < IN_F * NH; i += blockDim.x) {
        sW1[i] = Wg[i];
        sW3[i] = Wg[192 * NH + i];
    }
    __syncthreads();
    int w = threadIdx.x >> 5, lane = threadIdx.x & 31;
    int n = blockIdx.x * 8 + w;
    if (n >= NN) return;
    int h1 = lane >> 4, q = lane & 15;

    uint2 ua = g_fh[n * 64 + lane];
    uint2 ub = g_fh[n * 64 + 32 + lane];
    float2 fa0 = unpackh2(ua.x), fa1 = unpackh2(ua.y);
    float2 fb0 = unpackh2(ub.x), fb1 = unpackh2(ub.y);
    const float4* al4 = (const float4*)al;
    const float4* ar4 = (const float4*)ar;
    float4 a0 = al4[h1 * 16 + q], a1 = al4[(h1 + 2) * 16 + q];
    float4 r0 = ar4[h1 * 16 + q], r1 = ar4[(h1 + 2) * 16 + q];
    float el0 = fa0.x * a0.x + fa0.y * a0.y + fa1.x * a0.z + fa1.y * a0.w;
    float el1 = fb0.x * a1.x + fb0.y * a1.y + fb1.x * a1.z + fb1.y * a1.w;
    float er0 = fa0.x * r0.x + fa0.y * r0.y + fa1.x * r0.z + fa1.y * r0.w;
    float er1 = fb0.x * r1.x + fb0.y * r1.y + fb1.x * r1.z + fb1.y * r1.w;

    float4 xv = ((const float4*)x)[n * 32 + lane];
    float gx1[4], gx3[4];
    int r = 4 * lane;
    #pragma unroll
    for (int h = 0; h < 4; h++) {
        gx1[h] = xv.x * sW1[(r + 0) * 4 + h] + xv.y * sW1[(r + 1) * 4 + h]
               + xv.z * sW1[(r + 2) * 4 + h] + xv.w * sW1[(r + 3) * 4 + h];
        gx3[h] = xv.x * sW3[(r + 0) * 4 + h] + xv.y * sW3[(r + 1) * 4 + h]
               + xv.z * sW3[(r + 2) * 4 + h] + xv.w * sW3[(r + 3) * 4 + h];
    }

    #pragma unroll
    for (int d = 8; d >= 1; d >>= 1) {
        el0 += __shfl_down_sync(0xffffffffu, el0, d);
        el1 += __shfl_down_sync(0xffffffffu, el1, d);
        er0 += __shfl_down_sync(0xffffffffu, er0, d);
        er1 += __shfl_down_sync(0xffffffffu, er1, d);
    }
    #pragma unroll
    for (int d = 16; d >= 1; d >>= 1) {
        #pragma unroll
        for (int h = 0; h < 4; h++) {
            gx1[h] += __shfl_xor_sync(0xffffffffu, gx1[h], d);
            gx3[h] += __shfl_xor_sync(0xffffffffu, gx3[h], d);
        }
    }
    float elh1 = __shfl_sync(0xffffffffu, el0, 16);
    float elh3 = __shfl_sync(0xffffffffu, el1, 16);
    float erh1 = __shfl_sync(0xffffffffu, er0, 16);
    float erh3 = __shfl_sync(0xffffffffu, er1, 16);
    if (lane == 0) {
        g_eg[2 * n]     = make_float4(el0, elh1, el1, elh3);
        g_eg[2 * n + 1] = make_float4(gx3[0], gx3[1], gx3[2], gx3[3]);
        g_er4[n]        = make_float4(er0, erh1, er1, erh3);
        g_gx1[n]        = make_float4(gx1[0], gx1[1], gx1[2], gx1[3]);
    }
}

// ---------------- fused agg: 2 warps per node (even/odd CSR slots) --------------------
__global__ void k_agg(const float* __restrict__ Wg, const float* __restrict__ bg,
                      const float* __restrict__ bgat) {
    __shared__ float sW2[MAPF * NH];       // W_gate rows 128..191
    __shared__ float4 sAcc[4][32][3];      // [pair][lane][acc0, acc1, (zmx,zmy,-,-)]
    __shared__ float  sDen[4][8];          // den0-3, gxs0-3 from odd warp
    for (int i = threadIdx.x; i < MAPF * NH; i += blockDim.x) sW2[i] = Wg[IN_F * NH + i];
    __syncthreads();
    int w = threadIdx.x >> 5, lane = threadIdx.x & 31;
    int pair = w >> 1, half = w & 1;
    int d = blockIdx.x * 4 + pair;         // NN = 50000 = 4 * 12500: always valid
    int o0 = g_off[d], o1 = g_off[d + 1];
    int deg = o1 - o0;

    float4 er4 = g_er4[d];
    int h1 = lane >> 4, q = lane & 15;

    float zmx = -1e30f, zmy = -1e30f;
    float gxs0 = 0.f, gxs1 = 0.f, gxs2 = 0.f, gxs3 = 0.f;
    float den0 = 0.f, den1 = 0.f, den2 = 0.f, den3 = 0.f;
    float4 acc0 = {0.f, 0.f, 0.f, 0.f}, acc1 = {0.f, 0.f, 0.f, 0.f};

    // this warp handles CSR slots o0+half, o0+half+2, ... (unrolled by 2)
    int i = o0 + half;
    for (; i + 2 < o1; i += 4) {
        int s0 = g_srcs[i];
        int s1 = g_srcs[i + 2];
        unsigned zu0 = g_zh[s0 * 32 + lane];
        unsigned zu1 = g_zh[s1 * 32 + lane];
        float4 ev0 = g_eg[2 * s0];
        float4 ev1 = g_eg[2 * s1];
        float4 g30 = g_eg[2 * s0 + 1];
        float4 g31 = g_eg[2 * s1 + 1];
        uint2 ua0 = g_fh[s0 * 64 + lane];
        uint2 ub0 = g_fh[s0 * 64 + 32 + lane];
        uint2 ua1 = g_fh[s1 * 64 + lane];
        uint2 ub1 = g_fh[s1 * 64 + 32 + lane];
        {
            float2 zv = unpackh2(zu0);
            zmx = fmaxf(zmx, zv.x); zmy = fmaxf(zmy, zv.y);
            gxs0 += g30.x; gxs1 += g30.y; gxs2 += g30.z; gxs3 += g30.w;
            float e0 = ev0.x + er4.x, e1 = ev0.y + er4.y;
            float e2 = ev0.z + er4.z, e3 = ev0.w + er4.w;
            e0 = (e0 > 0.f) ? e0 : 0.2f * e0;
            e1 = (e1 > 0.f) ? e1 : 0.2f * e1;
            e2 = (e2 > 0.f) ? e2 : 0.2f * e2;
            e3 = (e3 > 0.f) ? e3 : 0.2f * e3;
            float w0 = __expf(e0), w1 = __expf(e1);
            float w2 = __expf(e2), w3 = __expf(e3);
            den0 += w0; den1 += w1; den2 += w2; den3 += w3;
            float2 fa0 = unpackh2(ua0.x), fa1 = unpackh2(ua0.y);
            float2 fb0 = unpackh2(ub0.x), fb1 = unpackh2(ub0.y);
            float wa = (h1 == 0) ? w0 : w1;
            float wb = (h1 == 0) ? w2 : w3;
            acc0.x += wa * fa0.x; acc0.y += wa * fa0.y; acc0.z += wa * fa1.x; acc0.w += wa * fa1.y;
            acc1.x += wb * fb0.x; acc1.y += wb * fb0.y; acc1.z += wb * fb1.x; acc1.w += wb * fb1.y;
        }
        {
            float2 zv = unpackh2(zu1);
            zmx = fmaxf(zmx, zv.x); zmy = fmaxf(zmy, zv.y);
            gxs0 += g31.x; gxs1 += g31.y; gxs2 += g31.z; gxs3 += g31.w;
            float e0 = ev1.x + er4.x, e1 = ev1.y + er4.y;
            float e2 = ev1.z + er4.z, e3 = ev1.w + er4.w;
            e0 = (e0 > 0.f) ? e0 : 0.2f * e0;
            e1 = (e1 > 0.f) ? e1 : 0.2f * e1;
            e2 = (e2 > 0.f) ? e2 : 0.2f * e2;
            e3 = (e3 > 0.f) ? e3 : 0.2f * e3;
            float w0 = __expf(e0), w1 = __expf(e1);
            float w2 = __expf(e2), w3 = __expf(e3);
            den0 += w0; den1 += w1; den2 += w2; den3 += w3;
            float2 fa0 = unpackh2(ua1.x), fa1 = unpackh2(ua1.y);
            float2 fb0 = unpackh2(ub1.x), fb1 = unpackh2(ub1.y);
            float wa = (h1 == 0) ? w0 : w1;
            float wb = (h1 == 0) ? w2 : w3;
            acc0.x += wa * fa0.x; acc0.y += wa * fa0.y; acc0.z += wa * fa1.x; acc0.w += wa * fa1.y;
            acc1.x += wb * fb0.x; acc1.y += wb * fb0.y; acc1.z += wb * fb1.x; acc1.w += wb * fb1.y;
        }
    }
    if (i < o1) {
        int s0 = g_srcs[i];
        unsigned zu0 = g_zh[s0 * 32 + lane];
        float4 ev0 = g_eg[2 * s0];
        float4 g30 = g_eg[2 * s0 + 1];
        uint2 ua0 = g_fh[s0 * 64 + lane];
        uint2 ub0 = g_fh[s0 * 64 + 32 + lane];
        float2 zv = unpackh2(zu0);
        zmx = fmaxf(zmx, zv.x); zmy = fmaxf(zmy, zv.y);
        gxs0 += g30.x; gxs1 += g30.y; gxs2 += g30.z; gxs3 += g30.w;
        float e0 = ev0.x + er4.x, e1 = ev0.y + er4.y;
        float e2 = ev0.z + er4.z, e3 = ev0.w + er4.w;
        e0 = (e0 > 0.f) ? e0 : 0.2f * e0;
        e1 = (e1 > 0.f) ? e1 : 0.2f * e1;
        e2 = (e2 > 0.f) ? e2 : 0.2f * e2;
        e3 = (e3 > 0.f) ? e3 : 0.2f * e3;
        float w0 = __expf(e0), w1 = __expf(e1);
        float w2 = __expf(e2), w3 = __expf(e3);
        den0 += w0; den1 += w1; den2 += w2; den3 += w3;
        float2 fa0 = unpackh2(ua0.x), fa1 = unpackh2(ua0.y);
        float2 fb0 = unpackh2(ub0.x), fb1 = unpackh2(ub0.y);
        float wa = (h1 == 0) ? w0 : w1;
        float wb = (h1 == 0) ? w2 : w3;
        acc0.x += wa * fa0.x; acc0.y += wa * fa0.y; acc0.z += wa * fa1.x; acc0.w += wa * fa1.y;
        acc1.x += wb * fb0.x; acc1.y += wb * fb0.y; acc1.z += wb * fb1.x; acc1.w += wb * fb1.y;
    }

    // ---- combine odd warp into even warp ----
    if (half == 1) {
        sAcc[pair][lane][0] = acc0;
        sAcc[pair][lane][1] = acc1;
        sAcc[pair][lane][2] = make_float4(zmx, zmy, 0.f, 0.f);
        if (lane == 0) {
            sDen[pair][0] = den0; sDen[pair][1] = den1;
            sDen[pair][2] = den2; sDen[pair][3] = den3;
            sDen[pair][4] = gxs0; sDen[pair][5] = gxs1;
            sDen[pair][6] = gxs2; sDen[pair][7] = gxs3;
        }
    }
    __syncthreads();
    if (half == 1) return;

    {
        float4 oa0 = sAcc[pair][lane][0];
        float4 oa1 = sAcc[pair][lane][1];
        float4 oz  = sAcc[pair][lane][2];
        acc0.x += oa0.x; acc0.y += oa0.y; acc0.z += oa0.z; acc0.w += oa0.w;
        acc1.x += oa1.x; acc1.y += oa1.y; acc1.z += oa1.z; acc1.w += oa1.w;
        zmx = fmaxf(zmx, oz.x); zmy = fmaxf(zmy, oz.y);
        den0 += sDen[pair][0]; den1 += sDen[pair][1];
        den2 += sDen[pair][2]; den3 += sDen[pair][3];
        gxs0 += sDen[pair][4]; gxs1 += sDen[pair][5];
        gxs2 += sDen[pair][6]; gxs3 += sDen[pair][7];
    }

    float4 gx1d = g_gx1[d];

    // ---- gate ----
    float inv = (deg > 0) ? 1.0f / (float)deg : 0.0f;
    if (deg == 0) { zmx = 0.f; zmy = 0.f; }
    float zr[4];
    int r2 = 2 * lane;
    #pragma unroll
    for (int h = 0; h < 4; h++)
        zr[h] = zmx * sW2[(r2 + 0) * 4 + h] + zmy * sW2[(r2 + 1) * 4 + h];
    #pragma unroll
    for (int dd = 16; dd >= 1; dd >>= 1) {
        #pragma unroll
        for (int h = 0; h < 4; h++) zr[h] += __shfl_xor_sync(0xffffffffu, zr[h], dd);
    }
    float gxs[4] = {gxs0, gxs1, gxs2, gxs3};
    float gx1a[4] = {gx1d.x, gx1d.y, gx1d.z, gx1d.w};
    float gate[4];
    #pragma unroll
    for (int h = 0; h < 4; h++) {
        float p = gx1a[h] + gxs[h] * inv + zr[h] + bg[h];
        gate[h] = 1.f / (1.f + __expf(-p));
    }

    // ---- normalize, bias, gate, head-average, store ----
    float4 bga = ((const float4*)bgat)[h1 * 16 + q];
    float4 bgb = ((const float4*)bgat)[(h1 + 2) * 16 + q];
    float4 a0, a1;
    if (deg > 0) {
        float ia = 1.f / ((h1 == 0) ? den0 : den1);
        float ib = 1.f / ((h1 == 0) ? den2 : den3);
        a0.x = acc0.x * ia + bga.x; a0.y = acc0.y * ia + bga.y;
        a0.z = acc0.z * ia + bga.z; a0.w = acc0.w * ia + bga.w;
        a1.x = acc1.x * ib + bgb.x; a1.y = acc1.y * ib + bgb.y;
        a1.z = acc1.z * ib + bgb.z; a1.w = acc1.w * ib + bgb.w;
    } else {
        a0 = bga; a1 = bgb;
    }
    float g0 = (h1 == 0) ? gate[0] : gate[1];
    float g1 = (h1 == 0) ? gate[2] : gate[3];
    float4 pp;
    pp.x = g0 * a0.x + g1 * a1.x;
    pp.y = g0 * a0.y + g1 * a1.y;
    pp.z = g0 * a0.z + g1 * a1.z;
    pp.w = g0 * a0.w + g1 * a1.w;
    pp.x += __shfl_xor_sync(0xffffffffu, pp.x, 16);
    pp.y += __shfl_xor_sync(0xffffffffu, pp.y, 16);
    pp.z += __shfl_xor_sync(0xffffffffu, pp.z, 16);
    pp.w += __shfl_xor_sync(0xffffffffu, pp.w, 16);
    pp.x *= 0.25f; pp.y *= 0.25f; pp.z *= 0.25f; pp.w *= 0.25f;
    if (lane < 16) ((float4*)g_gated)[d * 16 + lane] = pp;
}

// ---------------- merge GEMM (fp16 HMMA): out = [x | gated] @ W_merge + b_merge -------
__global__ void k_merge(const float* __restrict__ x, const float* __restrict__ Wm,
                        const float* __restrict__ bm, float* __restrict__ out) {
    __shared__ unsigned Ah[128][12];
    __shared__ unsigned Bs[8][72];
    int t = threadIdx.x;
    int rowBase = blockIdx.x * 128;
    int lane = t & 31, wrp = t >> 5;
    int wm = wrp & 3, wn = wrp >> 2;
    int g = lane >> 2, tig = lane & 3;

    float acc[2][4][4];
    #pragma unroll
    for (int mi = 0; mi < 2; mi++)
        #pragma unroll
        for (int ni = 0; ni < 4; ni++)
            #pragma unroll
            for (int q = 0; q < 4; q++) acc[mi][ni][q] = 0.f;

    int ar0 = t >> 2, akq = t & 3;
    int ar1 = ar0 + 64;
    int gr0 = rowBase + ar0; if (gr0 >= NN) gr0 = NN - 1;
    int gr1 = rowBase + ar1; if (gr1 >= NN) gr1 = NN - 1;
    int bkk = t >> 5, bl = t & 31;
    int n2 = bl * 2;

    for (int kt = 0; kt < 12; kt++) {
        int k0 = kt * 16 + akq * 4;
        float4 a0v, a1v;
        if (k0 < IN_F) {
            a0v = *(const float4*)&x[gr0 * IN_F + k0];
            a1v = *(const float4*)&x[gr1 * IN_F + k0];
        } else {
            a0v = *(const float4*)&g_gated[gr0 * OUT_F + (k0 - IN_F)];
            a1v = *(const float4*)&g_gated[gr1 * OUT_F + (k0 - IN_F)];
        }
        float2 bv0 = *(const float2*)&Wm[(kt * 16 + 2 * bkk) * 64 + n2];
        float2 bv1 = *(const float2*)&Wm[(kt * 16 + 2 * bkk + 1) * 64 + n2];
        uint2 ua0 = {packh2(a0v.x, a0v.y), packh2(a0v.z, a0v.w)};
        uint2 ua1 = {packh2(a1v.x, a1v.y), packh2(a1v.z, a1v.w)};
        uint2 ubv = {packh2(bv0.x, bv1.x), packh2(bv0.y, bv1.y)};
        *(uint2*)&Ah[ar0][akq * 2] = ua0;
        *(uint2*)&Ah[ar1][akq * 2] = ua1;
        *(uint2*)&Bs[bkk][n2]      = ubv;
        __syncthreads();
        unsigned a[2][4];
        #pragma unroll
        for (int mi = 0; mi < 2; mi++) {
            int rm = wm * 32 + mi * 16;
            a[mi][0] = Ah[rm + g][tig];
            a[mi][1] = Ah[rm + g + 8][tig];
            a[mi][2] = Ah[rm + g][tig + 4];
            a[mi][3] = Ah[rm + g + 8][tig + 4];
        }
        #pragma unroll
        for (int ni = 0; ni < 4; ni++) {
            int cn = wn * 32 + ni * 8;
            unsigned b0 = Bs[tig][cn + g];
            unsigned b1 = Bs[tig + 4][cn + g];
            hmma16(acc[0][ni], a[0][0], a[0][1], a[0][2], a[0][3], b0, b1);
            hmma16(acc[1][ni], a[1][0], a[1][1], a[1][2], a[1][3], b0, b1);
        }
        __syncthreads();
    }

    #pragma unroll
    for (int mi = 0; mi < 2; mi++) {
        #pragma unroll
        for (int ni = 0; ni < 4; ni++) {
            int lc = wn * 32 + ni * 8 + tig * 2;
            #pragma unroll
            for (int half = 0; half < 2; half++) {
                int r = rowBase + wm * 32 + mi * 16 + g + half * 8;
                if (r < NN) {
                    out[r * OUT_F + lc]     = acc[mi][ni][half * 2 + 0] + bm[lc];
                    out[r * OUT_F + lc + 1] = acc[mi][ni][half * 2 + 1] + bm[lc + 1];
                }
            }
        }
    }
}

// ---------------- launch ----------------
extern "C" void kernel_launch(void* const* d_in, const int* in_sizes, int n_in,
                              void* d_out, int out_size) {
    const float* x      = (const float*)d_in[0];
    const int*   ei     = (const int*)d_in[1];
    const float* W_gm   = (const float*)d_in[2];
    const float* b_gm   = (const float*)d_in[3];
    const float* W_gate = (const float*)d_in[4];
    const float* b_gate = (const float*)d_in[5];
    const float* W_fc   = (const float*)d_in[6];
    const float* attn_l = (const float*)d_in[7];
    const float* attn_r = (const float*)d_in[8];
    const float* b_gat  = (const float*)d_in[9];
    const float* W_mrg  = (const float*)d_in[10];
    const float* b_mrg  = (const float*)d_in[11];
    float* out = (float*)d_out;

    const int* src = ei;
    const int* dst = ei + EE;

    k_zero<<<(NN + 255) / 256, 256>>>();
    k_hist<<<(EE / 4 + 255) / 256, 256>>>(dst);
    k_scan1<<<NB, SCAN_BS>>>();
    k_gemm1<<<dim3((NN + 127) / 128, 5), 256>>>(x, W_gm, b_gm, W_fc);  // index 3: profiled
    k_scan2<<<1, 128>>>();
    k_scan3<<<NB, SCAN_BS>>>();
    k_scatter<<<(EE / 4 + 255) / 256, 256>>>(src, dst);
    k_pre<<<(NN + 7) / 8, 256>>>(x, attn_l, attn_r, W_gate);
    k_agg<<<NN / 4, 256>>>(W_gate, b_gate, b_gat);
    k_merge<<<(NN + 127) / 128, 256>>>(x, W_mrg, b_mrg, out);
}

// round 13
// speedup vs baseline: 1.1308x; 1.1308x over previous
#include <cuda_runtime.h>
#include <cuda_fp16.h>

#define NN   50000
#define EE   800000
#define IN_F 128
#define OUT_F 64
#define MAPF 64
#define NH   4
#define SCAN_BS 512
#define NB ((NN + SCAN_BS - 1) / SCAN_BS)   // 98

// ---------------- scratch (static device globals; no allocation) ----------------
__device__ int   g_count[NN];
__device__ int   g_off[NN + 1];
__device__ int   g_cursor[NN];
__device__ int   g_bsum[NB];
__device__ int   g_bbase[NB];
__device__ int   g_srcs[EE];
__device__ unsigned g_zh[NN * 32];   // z as fp16: 64 halfs/row
__device__ uint2    g_fh[NN * 64];   // feat as fp16: 256 halfs/row ([h][64])
__device__ float4 g_eg[NN * 2];      // [2n] = el(4 heads), [2n+1] = gx3 = x@W_gate[192:320]
__device__ float4 g_er4[NN];         // er (4 heads)
__device__ float4 g_gx1[NN];         // x@W_gate[0:128]
__device__ float g_gated[NN * OUT_F];

// ---------------- helpers ----------------
__device__ __forceinline__ void hmma16(float* c, unsigned a0, unsigned a1, unsigned a2,
                                       unsigned a3, unsigned b0, unsigned b1) {
    asm volatile(
        "mma.sync.aligned.m16n8k16.row.col.f32.f16.f16.f32 "
        "{%0,%1,%2,%3},{%4,%5,%6,%7},{%8,%9},{%0,%1,%2,%3};"
        : "+f"(c[0]), "+f"(c[1]), "+f"(c[2]), "+f"(c[3])
        : "r"(a0), "r"(a1), "r"(a2), "r"(a3), "r"(b0), "r"(b1));
}
__device__ __forceinline__ void ldsm4(unsigned& r0, unsigned& r1, unsigned& r2,
                                      unsigned& r3, unsigned saddr) {
    asm volatile("ldmatrix.sync.aligned.m8n8.x4.shared.b16 {%0,%1,%2,%3}, [%4];"
                 : "=r"(r0), "=r"(r1), "=r"(r2), "=r"(r3) : "r"(saddr));
}
__device__ __forceinline__ unsigned s2u(const void* p) {
    return (unsigned)__cvta_generic_to_shared(p);
}
__device__ __forceinline__ unsigned packh2(float a, float b) {
    __half2 h = __floats2half2_rn(a, b);
    return *(unsigned*)&h;
}
__device__ __forceinline__ float2 unpackh2(unsigned u) {
    return __half22float2(*(__half2*)&u);
}

// ---------------- CSR build ----------------
__global__ void k_zero() {
    int i = blockIdx.x * blockDim.x + threadIdx.x;
    if (i < NN) g_count[i] = 0;
}

__global__ void k_hist(const int* __restrict__ dst) {
    int e4 = blockIdx.x * blockDim.x + threadIdx.x;
    if (e4 < EE / 4) {
        int4 d = ((const int4*)dst)[e4];
        atomicAdd(&g_count[d.x], 1);
        atomicAdd(&g_count[d.y], 1);
        atomicAdd(&g_count[d.z], 1);
        atomicAdd(&g_count[d.w], 1);
    }
}

__global__ void k_scan1() {
    __shared__ int wsum[16];
    int b = blockIdx.x, t = threadIdx.x, lane = t & 31, w = t >> 5;
    int i = b * SCAN_BS + t;
    int v = (i < NN) ? g_count[i] : 0;
    int xs = v;
    #pragma unroll
    for (int d = 1; d < 32; d <<= 1) {
        int y = __shfl_up_sync(0xffffffffu, xs, d);
        if (lane >= d) xs += y;
    }
    if (lane == 31) wsum[w] = xs;
    __syncthreads();
    if (w == 0) {
        int s = (lane < 16) ? wsum[lane] : 0;
        #pragma unroll
        for (int d = 1; d < 16; d <<= 1) {
            int y = __shfl_up_sync(0xffffffffu, s, d);
            if (lane >= d) s += y;
        }
        if (lane < 16) wsum[lane] = s;
    }
    __syncthreads();
    int base = (w > 0) ? wsum[w - 1] : 0;
    if (i < NN) g_off[i] = base + xs - v;
    if (t == SCAN_BS - 1) g_bsum[b] = wsum[15];
}

__global__ void k_scan2() {
    __shared__ int ws[4];
    int t = threadIdx.x, lane = t & 31, w = t >> 5;
    int v = (t < NB) ? g_bsum[t] : 0;
    int xs = v;
    #pragma unroll
    for (int d = 1; d < 32; d <<= 1) {
        int y = __shfl_up_sync(0xffffffffu, xs, d);
        if (lane >= d) xs += y;
    }
    if (lane == 31) ws[w] = xs;
    __syncthreads();
    if (t == 0) {
        int a = 0;
        #pragma unroll
        for (int k = 0; k < 4; k++) { int tmp = ws[k]; ws[k] = a; a += tmp; }
    }
    __syncthreads();
    if (t < NB) g_bbase[t] = ws[w] + xs - v;
}

__global__ void k_scan3() {
    int b = blockIdx.x, t = threadIdx.x;
    int i = b * SCAN_BS + t;
    if (i < NN) {
        int o = g_off[i] + g_bbase[b];
        g_off[i] = o;
        g_cursor[i] = o;
    }
    if (i == 0) g_off[NN] = EE;
}

__global__ void k_scatter(const int* __restrict__ src, const int* __restrict__ dst) {
    int e4 = blockIdx.x * blockDim.x + threadIdx.x;
    if (e4 < EE / 4) {
        int4 d = ((const int4*)dst)[e4];
        int4 s = ((const int4*)src)[e4];
        g_srcs[atomicAdd(&g_cursor[d.x], 1)] = s.x;
        g_srcs[atomicAdd(&g_cursor[d.y], 1)] = s.y;
        g_srcs[atomicAdd(&g_cursor[d.z], 1)] = s.z;
        g_srcs[atomicAdd(&g_cursor[d.w], 1)] = s.w;
    }
}

// ---------------- GEMM1 (fp16 HMMA + ldmatrix): z_h (nt=0), feat_h (nt=1..4) ---------
// A smem: Ah[m][12 words], k halfs packed (rows 48B, 16B-aligned).
// B smem: Bk[n][12 words], K-MAJOR rows (n rows of 16 k-halfs, 48B stride).
__global__ void k_gemm1(const float* __restrict__ x,
                        const float* __restrict__ Wgm, const float* __restrict__ bgm,
                        const float* __restrict__ Wfc) {
    __shared__ unsigned Ah[128][12];
    __shared__ unsigned Bk[64][12];
    int t = threadIdx.x;
    int nt = blockIdx.y;
    int rowBase = blockIdx.x * 128;
    const float* W; int ldw, colBase;
    if (nt == 0) { W = Wgm; ldw = 64;  colBase = 0; }
    else         { W = Wfc; ldw = 256; colBase = (nt - 1) * 64; }

    int lane = t & 31, wrp = t >> 5;
    int wm = wrp & 3, wn = wrp >> 2;

    float acc[2][4][4];
    #pragma unroll
    for (int mi = 0; mi < 2; mi++)
        #pragma unroll
        for (int ni = 0; ni < 4; ni++)
            #pragma unroll
            for (int q = 0; q < 4; q++) acc[mi][ni][q] = 0.f;

    int ar0 = t >> 2, akq = t & 3;     // A loader: row, k-quad
    int ar1 = ar0 + 64;
    int gr0 = rowBase + ar0; if (gr0 >= NN) gr0 = NN - 1;
    int gr1 = rowBase + ar1; if (gr1 >= NN) gr1 = NN - 1;
    int bn = t & 63, bkq = t >> 6;     // B loader: n 0..63, k-quad 0..3

    // ldmatrix source addresses (per-warp)
    int lrow = lane & 15, lhalf = lane >> 4;   // row-within-16, k-half (16B)
    unsigned aAddr0 = s2u(&Ah[wm * 32 + lrow][lhalf * 4]);
    unsigned aAddr1 = s2u(&Ah[wm * 32 + 16 + lrow][lhalf * 4]);
    unsigned bAddr0 = s2u(&Bk[wn * 32 + lrow][lhalf * 4]);
    unsigned bAddr1 = s2u(&Bk[wn * 32 + 16 + lrow][lhalf * 4]);

    for (int kt = 0; kt < 8; kt++) {
        float4 a0v = *(const float4*)&x[gr0 * IN_F + kt * 16 + akq * 4];
        float4 a1v = *(const float4*)&x[gr1 * IN_F + kt * 16 + akq * 4];
        // B: 4 k-values along column n (transpose into K-major smem)
        int kb = kt * 16 + bkq * 4;
        float w0 = W[(kb + 0) * ldw + colBase + bn];
        float w1 = W[(kb + 1) * ldw + colBase + bn];
        float w2 = W[(kb + 2) * ldw + colBase + bn];
        float w3 = W[(kb + 3) * ldw + colBase + bn];
        uint2 ua0 = {packh2(a0v.x, a0v.y), packh2(a0v.z, a0v.w)};
        uint2 ua1 = {packh2(a1v.x, a1v.y), packh2(a1v.z, a1v.w)};
        uint2 ubv = {packh2(w0, w1), packh2(w2, w3)};
        *(uint2*)&Ah[ar0][akq * 2] = ua0;
        *(uint2*)&Ah[ar1][akq * 2] = ua1;
        *(uint2*)&Bk[bn][bkq * 2]  = ubv;
        __syncthreads();
        unsigned a[2][4], b[2][4];
        ldsm4(a[0][0], a[0][1], a[0][2], a[0][3], aAddr0);
        ldsm4(a[1][0], a[1][1], a[1][2], a[1][3], aAddr1);
        // b[half][...]: m0 = n0-7 k0-7 (b0 of ni), m1 = n8-15 k0-7 (b0 of ni+1),
        //               m2 = n0-7 k8-15 (b1 of ni), m3 = n8-15 k8-15 (b1 of ni+1)
        ldsm4(b[0][0], b[0][1], b[0][2], b[0][3], bAddr0);
        ldsm4(b[1][0], b[1][1], b[1][2], b[1][3], bAddr1);
        #pragma unroll
        for (int ni = 0; ni < 4; ni++) {
            unsigned b0 = b[ni >> 1][ni & 1];
            unsigned b1 = b[ni >> 1][(ni & 1) + 2];
            hmma16(acc[0][ni], a[0][0], a[0][1], a[0][2], a[0][3], b0, b1);
            hmma16(acc[1][ni], a[1][0], a[1][1], a[1][2], a[1][3], b0, b1);
        }
        __syncthreads();
    }

    int g = lane >> 2, tig = lane & 3;
    #pragma unroll
    for (int mi = 0; mi < 2; mi++) {
        #pragma unroll
        for (int ni = 0; ni < 4; ni++) {
            int lc = wn * 32 + ni * 8 + tig * 2;
            #pragma unroll
            for (int half = 0; half < 2; half++) {
                int r = rowBase + wm * 32 + mi * 16 + g + half * 8;
                if (r < NN) {
                    float v0 = acc[mi][ni][half * 2 + 0];
                    float v1 = acc[mi][ni][half * 2 + 1];
                    if (nt == 0) {
                        g_zh[r * 32 + (lc >> 1)] = packh2(v0 + bgm[lc], v1 + bgm[lc + 1]);
                    } else {
                        ((unsigned*)g_fh)[r * 128 + ((colBase + lc) >> 1)] = packh2(v0, v1);
                    }
                }
            }
        }
    }
}

// ---------------- k_pre: el/er + gx1/gx3 per node (warp per node) ----------------
__global__ void k_pre(const float* __restrict__ x,
                      const float* __restrict__ al, const float* __restrict__ ar,
                      const float* __restrict__ Wg) {
    __shared__ float sW1[IN_F * NH];   // W_gate rows 0..127
    __shared__ float sW3[IN_F * NH];   // W_gate rows 192..319
    for (int i = threadIdx.x; i < IN_F * NH; i += blockDim.x) {
        sW1[i] = Wg[i];
        sW3[i] = Wg[192 * NH + i];
    }
    __syncthreads();
    int w = threadIdx.x >> 5, lane = threadIdx.x & 31;
    int n = blockIdx.x * 8 + w;
    if (n >= NN) return;
    int h1 = lane >> 4, q = lane & 15;

    uint2 ua = g_fh[n * 64 + lane];
    uint2 ub = g_fh[n * 64 + 32 + lane];
    float2 fa0 = unpackh2(ua.x), fa1 = unpackh2(ua.y);
    float2 fb0 = unpackh2(ub.x), fb1 = unpackh2(ub.y);
    const float4* al4 = (const float4*)al;
    const float4* ar4 = (const float4*)ar;
    float4 a0 = al4[h1 * 16 + q], a1 = al4[(h1 + 2) * 16 + q];
    float4 r0 = ar4[h1 * 16 + q], r1 = ar4[(h1 + 2) * 16 + q];
    float el0 = fa0.x * a0.x + fa0.y * a0.y + fa1.x * a0.z + fa1.y * a0.w;
    float el1 = fb0.x * a1.x + fb0.y * a1.y + fb1.x * a1.z + fb1.y * a1.w;
    float er0 = fa0.x * r0.x + fa0.y * r0.y + fa1.x * r0.z + fa1.y * r0.w;
    float er1 = fb0.x * r1.x + fb0.y * r1.y + fb1.x * r1.z + fb1.y * r1.w;

    float4 xv = ((const float4*)x)[n * 32 + lane];
    float gx1[4], gx3[4];
    int r = 4 * lane;
    #pragma unroll
    for (int h = 0; h < 4; h++) {
        gx1[h] = xv.x * sW1[(r + 0) * 4 + h] + xv.y * sW1[(r + 1) * 4 + h]
               + xv.z * sW1[(r + 2) * 4 + h] + xv.w * sW1[(r + 3) * 4 + h];
        gx3[h] = xv.x * sW3[(r + 0) * 4 + h] + xv.y * sW3[(r + 1) * 4 + h]
               + xv.z * sW3[(r + 2) * 4 + h] + xv.w * sW3[(r + 3) * 4 + h];
    }

    #pragma unroll
    for (int d = 8; d >= 1; d >>= 1) {
        el0 += __shfl_down_sync(0xffffffffu, el0, d);
        el1 += __shfl_down_sync(0xffffffffu, el1, d);
        er0 += __shfl_down_sync(0xffffffffu, er0, d);
        er1 += __shfl_down_sync(0xffffffffu, er1, d);
    }
    #pragma unroll
    for (int d = 16; d >= 1; d >>= 1) {
        #pragma unroll
        for (int h = 0; h < 4; h++) {
            gx1[h] += __shfl_xor_sync(0xffffffffu, gx1[h], d);
            gx3[h] += __shfl_xor_sync(0xffffffffu, gx3[h], d);
        }
    }
    float elh1 = __shfl_sync(0xffffffffu, el0, 16);
    float elh3 = __shfl_sync(0xffffffffu, el1, 16);
    float erh1 = __shfl_sync(0xffffffffu, er0, 16);
    float erh3 = __shfl_sync(0xffffffffu, er1, 16);
    if (lane == 0) {
        g_eg[2 * n]     = make_float4(el0, elh1, el1, elh3);
        g_eg[2 * n + 1] = make_float4(gx3[0], gx3[1], gx3[2], gx3[3]);
        g_er4[n]        = make_float4(er0, erh1, er1, erh3);
        g_gx1[n]        = make_float4(gx1[0], gx1[1], gx1[2], gx1[3]);
    }
}

// ---------------- fused single-pass agg (round-8 baseline) ----------------------------
__global__ void k_agg(const float* __restrict__ Wg, const float* __restrict__ bg,
                      const float* __restrict__ bgat) {
    __shared__ float sW2[MAPF * NH];   // W_gate rows 128..191
    for (int i = threadIdx.x; i < MAPF * NH; i += blockDim.x) sW2[i] = Wg[IN_F * NH + i];
    __syncthreads();
    int w = threadIdx.x >> 5, lane = threadIdx.x & 31;
    int d = blockIdx.x * 8 + w;
    if (d >= NN) return;
    int o0 = g_off[d], o1 = g_off[d + 1];
    int deg = o1 - o0;

    float4 er4 = g_er4[d];
    float4 gx1d = g_gx1[d];
    int h1 = lane >> 4, q = lane & 15;

    float zmx = -1e30f, zmy = -1e30f;
    float gxs0 = 0.f, gxs1 = 0.f, gxs2 = 0.f, gxs3 = 0.f;
    float den0 = 0.f, den1 = 0.f, den2 = 0.f, den3 = 0.f;
    float4 acc0 = {0.f, 0.f, 0.f, 0.f}, acc1 = {0.f, 0.f, 0.f, 0.f};

    int i = o0;
    if (deg >= 4) {
        int last = o1 - 1;
        int p0 = g_srcs[i], p1 = g_srcs[i + 1], p2 = g_srcs[i + 2], p3 = g_srcs[i + 3];
        for (; i + 3 < o1; i += 4) {
            int s[4] = {p0, p1, p2, p3};
            unsigned zu[4]; float4 ev[4], g3[4]; uint2 ua[4], ub[4];
            #pragma unroll
            for (int j = 0; j < 4; j++) {
                zu[j] = g_zh[s[j] * 32 + lane];
                ev[j] = g_eg[2 * s[j]];
                g3[j] = g_eg[2 * s[j] + 1];
                ua[j] = g_fh[s[j] * 64 + lane];
                ub[j] = g_fh[s[j] * 64 + 32 + lane];
            }
            int nb = i + 4;
            p0 = g_srcs[min(nb,     last)];
            p1 = g_srcs[min(nb + 1, last)];
            p2 = g_srcs[min(nb + 2, last)];
            p3 = g_srcs[min(nb + 3, last)];
            #pragma unroll
            for (int j = 0; j < 4; j++) {
                float2 zv = unpackh2(zu[j]);
                zmx = fmaxf(zmx, zv.x); zmy = fmaxf(zmy, zv.y);
                gxs0 += g3[j].x; gxs1 += g3[j].y; gxs2 += g3[j].z; gxs3 += g3[j].w;
                float e0 = ev[j].x + er4.x, e1 = ev[j].y + er4.y;
                float e2 = ev[j].z + er4.z, e3 = ev[j].w + er4.w;
                e0 = (e0 > 0.f) ? e0 : 0.2f * e0;
                e1 = (e1 > 0.f) ? e1 : 0.2f * e1;
                e2 = (e2 > 0.f) ? e2 : 0.2f * e2;
                e3 = (e3 > 0.f) ? e3 : 0.2f * e3;
                float w0 = __expf(e0), w1 = __expf(e1);
                float w2 = __expf(e2), w3 = __expf(e3);
                den0 += w0; den1 += w1; den2 += w2; den3 += w3;
                float2 fa0 = unpackh2(ua[j].x), fa1 = unpackh2(ua[j].y);
                float2 fb0 = unpackh2(ub[j].x), fb1 = unpackh2(ub[j].y);
                float wa = (h1 == 0) ? w0 : w1;
                float wb = (h1 == 0) ? w2 : w3;
                acc0.x += wa * fa0.x; acc0.y += wa * fa0.y; acc0.z += wa * fa1.x; acc0.w += wa * fa1.y;
                acc1.x += wb * fb0.x; acc1.y += wb * fb0.y; acc1.z += wb * fb1.x; acc1.w += wb * fb1.y;
            }
        }
    }
    for (; i < o1; i++) {
        int s0 = g_srcs[i];
        unsigned zu0 = g_zh[s0 * 32 + lane];
        float4 ev0 = g_eg[2 * s0];
        float4 g30 = g_eg[2 * s0 + 1];
        uint2 ua0 = g_fh[s0 * 64 + lane];
        uint2 ub0 = g_fh[s0 * 64 + 32 + lane];
        float2 zv = unpackh2(zu0);
        zmx = fmaxf(zmx, zv.x); zmy = fmaxf(zmy, zv.y);
        gxs0 += g30.x; gxs1 += g30.y; gxs2 += g30.z; gxs3 += g30.w;
        float e0 = ev0.x + er4.x, e1 = ev0.y + er4.y;
        float e2 = ev0.z + er4.z, e3 = ev0.w + er4.w;
        e0 = (e0 > 0.f) ? e0 : 0.2f * e0;
        e1 = (e1 > 0.f) ? e1 : 0.2f * e1;
        e2 = (e2 > 0.f) ? e2 : 0.2f * e2;
        e3 = (e3 > 0.f) ? e3 : 0.2f * e3;
        float w0 = __expf(e0), w1 = __expf(e1);
        float w2 = __expf(e2), w3 = __expf(e3);
        den0 += w0; den1 += w1; den2 += w2; den3 += w3;
        float2 fa0 = unpackh2(ua0.x), fa1 = unpackh2(ua0.y);
        float2 fb0 = unpackh2(ub0.x), fb1 = unpackh2(ub0.y);
        float wa = (h1 == 0) ? w0 : w1;
        float wb = (h1 == 0) ? w2 : w3;
        acc0.x += wa * fa0.x; acc0.y += wa * fa0.y; acc0.z += wa * fa1.x; acc0.w += wa * fa1.y;
        acc1.x += wb * fb0.x; acc1.y += wb * fb0.y; acc1.z += wb * fb1.x; acc1.w += wb * fb1.y;
    }

    // ---- gate ----
    float inv = (deg > 0) ? 1.0f / (float)deg : 0.0f;
    if (deg == 0) { zmx = 0.f; zmy = 0.f; }
    float zr[4];
    int r2 = 2 * lane;
    #pragma unroll
    for (int h = 0; h < 4; h++)
        zr[h] = zmx * sW2[(r2 + 0) * 4 + h] + zmy * sW2[(r2 + 1) * 4 + h];
    #pragma unroll
    for (int dd = 16; dd >= 1; dd >>= 1) {
        #pragma unroll
        for (int h = 0; h < 4; h++) zr[h] += __shfl_xor_sync(0xffffffffu, zr[h], dd);
    }
    float gxs[4] = {gxs0, gxs1, gxs2, gxs3};
    float gx1a[4] = {gx1d.x, gx1d.y, gx1d.z, gx1d.w};
    float gate[4];
    #pragma unroll
    for (int h = 0; h < 4; h++) {
        float p = gx1a[h] + gxs[h] * inv + zr[h] + bg[h];
        gate[h] = 1.f / (1.f + __expf(-p));
    }

    // ---- normalize, bias, gate, head-average, store ----
    float4 bga = ((const float4*)bgat)[h1 * 16 + q];
    float4 bgb = ((const float4*)bgat)[(h1 + 2) * 16 + q];
    float4 a0, a1;
    if (deg > 0) {
        float ia = 1.f / ((h1 == 0) ? den0 : den1);
        float ib = 1.f / ((h1 == 0) ? den2 : den3);
        a0.x = acc0.x * ia + bga.x; a0.y = acc0.y * ia + bga.y;
        a0.z = acc0.z * ia + bga.z; a0.w = acc0.w * ia + bga.w;
        a1.x = acc1.x * ib + bgb.x; a1.y = acc1.y * ib + bgb.y;
        a1.z = acc1.z * ib + bgb.z; a1.w = acc1.w * ib + bgb.w;
    } else {
        a0 = bga; a1 = bgb;
    }
    float g0 = (h1 == 0) ? gate[0] : gate[1];
    float g1 = (h1 == 0) ? gate[2] : gate[3];
    float4 pp;
    pp.x = g0 * a0.x + g1 * a1.x;
    pp.y = g0 * a0.y + g1 * a1.y;
    pp.z = g0 * a0.z + g1 * a1.z;
    pp.w = g0 * a0.w + g1 * a1.w;
    pp.x += __shfl_xor_sync(0xffffffffu, pp.x, 16);
    pp.y += __shfl_xor_sync(0xffffffffu, pp.y, 16);
    pp.z += __shfl_xor_sync(0xffffffffu, pp.z, 16);
    pp.w += __shfl_xor_sync(0xffffffffu, pp.w, 16);
    pp.x *= 0.25f; pp.y *= 0.25f; pp.z *= 0.25f; pp.w *= 0.25f;
    if (lane < 16) ((float4*)g_gated)[d * 16 + lane] = pp;
}

// ---------------- merge GEMM (fp16 HMMA + ldmatrix) -----------------------------------
__global__ void k_merge(const float* __restrict__ x, const float* __restrict__ Wm,
                        const float* __restrict__ bm, float* __restrict__ out) {
    __shared__ unsigned Ah[128][12];
    __shared__ unsigned Bk[64][12];
    int t = threadIdx.x;
    int rowBase = blockIdx.x * 128;
    int lane = t & 31, wrp = t >> 5;
    int wm = wrp & 3, wn = wrp >> 2;

    float acc[2][4][4];
    #pragma unroll
    for (int mi = 0; mi < 2; mi++)
        #pragma unroll
        for (int ni = 0; ni < 4; ni++)
            #pragma unroll
            for (int q = 0; q < 4; q++) acc[mi][ni][q] = 0.f;

    int ar0 = t >> 2, akq = t & 3;
    int ar1 = ar0 + 64;
    int gr0 = rowBase + ar0; if (gr0 >= NN) gr0 = NN - 1;
    int gr1 = rowBase + ar1; if (gr1 >= NN) gr1 = NN - 1;
    int bn = t & 63, bkq = t >> 6;

    int lrow = lane & 15, lhalf = lane >> 4;
    unsigned aAddr0 = s2u(&Ah[wm * 32 + lrow][lhalf * 4]);
    unsigned aAddr1 = s2u(&Ah[wm * 32 + 16 + lrow][lhalf * 4]);
    unsigned bAddr0 = s2u(&Bk[wn * 32 + lrow][lhalf * 4]);
    unsigned bAddr1 = s2u(&Bk[wn * 32 + 16 + lrow][lhalf * 4]);

    for (int kt = 0; kt < 12; kt++) {
        int k0 = kt * 16 + akq * 4;
        float4 a0v, a1v;
        if (k0 < IN_F) {
            a0v = *(const float4*)&x[gr0 * IN_F + k0];
            a1v = *(const float4*)&x[gr1 * IN_F + k0];
        } else {
            a0v = *(const float4*)&g_gated[gr0 * OUT_F + (k0 - IN_F)];
            a1v = *(const float4*)&g_gated[gr1 * OUT_F + (k0 - IN_F)];
        }
        int kb = kt * 16 + bkq * 4;
        float w0 = Wm[(kb + 0) * 64 + bn];
        float w1 = Wm[(kb + 1) * 64 + bn];
        float w2 = Wm[(kb + 2) * 64 + bn];
        float w3 = Wm[(kb + 3) * 64 + bn];
        uint2 ua0 = {packh2(a0v.x, a0v.y), packh2(a0v.z, a0v.w)};
        uint2 ua1 = {packh2(a1v.x, a1v.y), packh2(a1v.z, a1v.w)};
        uint2 ubv = {packh2(w0, w1), packh2(w2, w3)};
        *(uint2*)&Ah[ar0][akq * 2] = ua0;
        *(uint2*)&Ah[ar1][akq * 2] = ua1;
        *(uint2*)&Bk[bn][bkq * 2]  = ubv;
        __syncthreads();
        unsigned a[2][4], b[2][4];
        ldsm4(a[0][0], a[0][1], a[0][2], a[0][3], aAddr0);
        ldsm4(a[1][0], a[1][1], a[1][2], a[1][3], aAddr1);
        ldsm4(b[0][0], b[0][1], b[0][2], b[0][3], bAddr0);
        ldsm4(b[1][0], b[1][1], b[1][2], b[1][3], bAddr1);
        #pragma unroll
        for (int ni = 0; ni < 4; ni++) {
            unsigned b0 = b[ni >> 1][ni & 1];
            unsigned b1 = b[ni >> 1][(ni & 1) + 2];
            hmma16(acc[0][ni], a[0][0], a[0][1], a[0][2], a[0][3], b0, b1);
            hmma16(acc[1][ni], a[1][0], a[1][1], a[1][2], a[1][3], b0, b1);
        }
        __syncthreads();
    }

    int g = lane >> 2, tig = lane & 3;
    #pragma unroll
    for (int mi = 0; mi < 2; mi++) {
        #pragma unroll
        for (int ni = 0; ni < 4; ni++) {
            int lc = wn * 32 + ni * 8 + tig * 2;
            #pragma unroll
            for (int half = 0; half < 2; half++) {
                int r = rowBase + wm * 32 + mi * 16 + g + half * 8;
                if (r < NN) {
                    out[r * OUT_F + lc]     = acc[mi][ni][half * 2 + 0] + bm[lc];
                    out[r * OUT_F + lc + 1] = acc[mi][ni][half * 2 + 1] + bm[lc + 1];
                }
            }
        }
    }
}

// ---------------- launch (serial, round-8 order) ----------------
extern "C" void kernel_launch(void* const* d_in, const int* in_sizes, int n_in,
                              void* d_out, int out_size) {
    const float* x      = (const float*)d_in[0];
    const int*   ei     = (const int*)d_in[1];
    const float* W_gm   = (const float*)d_in[2];
    const float* b_gm   = (const float*)d_in[3];
    const float* W_gate = (const float*)d_in[4];
    const float* b_gate = (const float*)d_in[5];
    const float* W_fc   = (const float*)d_in[6];
    const float* attn_l = (const float*)d_in[7];
    const float* attn_r = (const float*)d_in[8];
    const float* b_gat  = (const float*)d_in[9];
    const float* W_mrg  = (const float*)d_in[10];
    const float* b_mrg  = (const float*)d_in[11];
    float* out = (float*)d_out;

    const int* src = ei;
    const int* dst = ei + EE;

    k_zero<<<(NN + 255) / 256, 256>>>();
    k_hist<<<(EE / 4 + 255) / 256, 256>>>(dst);
    k_scan1<<<NB, SCAN_BS>>>();
    k_gemm1<<<dim3((NN + 127) / 128, 5), 256>>>(x, W_gm, b_gm, W_fc);  // index 3: profiled
    k_scan2<<<1, 128>>>();
    k_scan3<<<NB, SCAN_BS>>>();
    k_scatter<<<(EE / 4 + 255) / 256, 256>>>(src, dst);
    k_pre<<<(NN + 7) / 8, 256>>>(x, attn_l, attn_r, W_gate);
    k_agg<<<(NN + 7) / 8, 256>>>(W_gate, b_gate, b_gat);
    k_merge<<<(NN + 127) / 128, 256>>>(x, W_mrg, b_mrg, out);
}